// round 15
// baseline (speedup 1.0000x reference)
#include <cuda_runtime.h>
#include <cuda_fp16.h>
#include <cstdint>

#define NHEADS 16
#define DHEAD  64
#define NB     4
#define SEQ    2048
#define DMODEL 1024
#define NBH    (NB * NHEADS)   // 64
#define MTOK   (NB * SEQ)      // 8192

#define QSCALE 0.18033688011112042f   /* 0.125 * log2(e) */

// ---- scratch ----
__device__ __half g_xr[(size_t)MTOK * DMODEL];
__device__ __half g_wt[4][(size_t)DMODEL * DMODEL];
__device__ __half g_q[(size_t)NBH * SEQ * DHEAD];    // [bh][s][d], *QSCALE
__device__ __half g_k[(size_t)NBH * SEQ * DHEAD];    // [bh][s][d]
__device__ __half g_v[(size_t)NBH * DHEAD * SEQ];    // [bh][d][s]
__device__ __half g_c[(size_t)MTOK * DMODEL];        // ctx fp16

__device__ __forceinline__ void mma16h(float c[4], const uint32_t a[4],
                                       uint32_t b0, uint32_t b1) {
    asm volatile(
        "mma.sync.aligned.m16n8k16.row.col.f32.f16.f16.f32 "
        "{%0,%1,%2,%3},{%4,%5,%6,%7},{%8,%9},{%0,%1,%2,%3};"
        : "+f"(c[0]), "+f"(c[1]), "+f"(c[2]), "+f"(c[3])
        : "r"(a[0]), "r"(a[1]), "r"(a[2]), "r"(a[3]), "r"(b0), "r"(b1));
}
__device__ __forceinline__ void ldsm4(uint32_t& r0, uint32_t& r1, uint32_t& r2, uint32_t& r3,
                                      uint32_t addr) {
    asm volatile("ldmatrix.sync.aligned.m8n8.x4.shared.b16 {%0,%1,%2,%3}, [%4];"
                 : "=r"(r0), "=r"(r1), "=r"(r2), "=r"(r3) : "r"(addr));
}
__device__ __forceinline__ void cpa16(uint32_t dst, const void* src) {
    asm volatile("cp.async.cg.shared.global [%0], [%1], 16;" :: "r"(dst), "l"(src));
}
__device__ __forceinline__ uint32_t h2u(float a, float b) {
    __half2 h = __floats2half2_rn(a, b);
    return *(uint32_t*)&h;
}
__device__ __forceinline__ uint32_t cvt_h2(float lo, float hi) {
    uint32_t d;
    asm("cvt.rn.f16x2.f32 %0, %1, %2;" : "=r"(d) : "f"(hi), "f"(lo));
    return d;
}
__device__ __forceinline__ uint32_t ex2h2(uint32_t x) {
    uint32_t d; asm("ex2.approx.f16x2 %0, %1;" : "=r"(d) : "r"(x)); return d;
}

// ============================================================================
// Pre-pass 1: x -> fp16   (R12 form)
// ============================================================================
__global__ void k_roundx(const float4* __restrict__ X)
{
    const size_t i = (size_t)blockIdx.x * blockDim.x + threadIdx.x;
    float4 v = X[i];
    ((uint2*)g_xr)[i] = make_uint2(h2u(v.x, v.y), h2u(v.z, v.w));
}

// ============================================================================
// Pre-pass 2: transpose weights to [n][k] fp16   (R12 form)
// ============================================================================
__global__ void k_trw(const float* __restrict__ Wq, const float* __restrict__ Wk,
                      const float* __restrict__ Wv, const float* __restrict__ Wo)
{
    const int p = blockIdx.z;
    const float* W = (p == 0) ? Wq : (p == 1) ? Wk : (p == 2) ? Wv : Wo;
    __shared__ float t[32][33];
    const int n0 = blockIdx.x * 32, k0 = blockIdx.y * 32;
    const int tx = threadIdx.x, ty = threadIdx.y;
    #pragma unroll
    for (int i = 0; i < 4; i++)
        t[ty + 8 * i][tx] = W[(size_t)(k0 + ty + 8 * i) * DMODEL + n0 + tx];
    __syncthreads();
    __half* out = g_wt[p];
    #pragma unroll
    for (int i = 0; i < 4; i++)
        out[(size_t)(n0 + ty + 8 * i) * DMODEL + k0 + tx] = __float2half_rn(t[tx][ty + 8 * i]);
}

// ============================================================================
// Projection GEMM v2 (flash-shaped): 128 thr (4 warps), 64x128 tile,
// warp tile 32x64, 3-stage x 24KB = 72KB -> 3 CTAs/SM (3 barrier domains).
// mode 0/1/2 = Q/K/V proj (A=g_xr), mode 3 = output proj (A=g_c, writes f32).
// Stage layout: A [64][64]h @ +0 (8KB), B [128][64]h @ +8192 (16KB).
// ============================================================================
#define SMEM_PROJ 73728
#define NKT (DMODEL / 64)   // 16

__global__ void __launch_bounds__(128, 3) k_proj(int mode_base, float* __restrict__ Out)
{
    extern __shared__ char sm[];
    const uint32_t sb = (uint32_t)__cvta_generic_to_shared(sm);

    const int mode = mode_base + blockIdx.z;
    const __half* A = (mode < 3) ? g_xr : g_c;
    const __half* Bt = g_wt[mode];

    const int tid = threadIdx.x, lane = tid & 31, warp = tid >> 5;
    const int wm = (warp & 1) * 32, wn = (warp >> 1) * 64;
    const int m0 = blockIdx.y * 64, n0 = blockIdx.x * 128;

    float acc[2][8][4];
    #pragma unroll
    for (int i = 0; i < 2; i++)
        #pragma unroll
        for (int j = 0; j < 8; j++)
            #pragma unroll
            for (int q = 0; q < 4; q++) acc[i][j][q] = 0.f;

    // loaders: A 64 rows x 8 chunks (2 thr/row, 4 chunks each); B 128 rows x 8
    // chunks (1 thr/row, 8 chunks each)
    const int lr = tid >> 1, lh = tid & 1;
    const __half* Ap = A  + (size_t)(m0 + lr) * DMODEL + lh * 32;
    const __half* Bp = Bt + (size_t)(n0 + tid) * DMODEL;
    uint32_t aoffs[4], boffs[8];
    #pragma unroll
    for (int i = 0; i < 4; i++) {
        const int c = 4 * lh + i;
        aoffs[i] = lr * 128 + ((c ^ (lr & 7)) << 4);
    }
    #pragma unroll
    for (int c = 0; c < 8; c++)
        boffs[c] = 8192 + tid * 128 + ((c ^ (tid & 7)) << 4);

    auto load = [&](int kt, int s) {
        if (kt < NKT) {
            const uint32_t base = sb + s * 24576;
            const __half* a = Ap + kt * 64;
            const __half* b = Bp + kt * 64;
            #pragma unroll
            for (int i = 0; i < 4; i++) cpa16(base + aoffs[i], a + 8 * i);
            #pragma unroll
            for (int c = 0; c < 8; c++) cpa16(base + boffs[c], b + 8 * c);
        }
        asm volatile("cp.async.commit_group;");
    };

    // lane-constant swizzled sub-offsets
    const int lrow = ((lane >> 3) & 1) * 8 + (lane & 7);
    const int lch  = lane >> 4;
    uint32_t LK[4];
    #pragma unroll
    for (int s = 0; s < 4; s++)
        LK[s] = lrow * 128 + (((2 * s + lch) ^ (lrow & 7)) << 4);

    auto step = [&](int kt, int buf, int pbuf) {
        asm volatile("cp.async.wait_group 1;");
        __syncthreads();
        load(kt + 2, pbuf);

        const uint32_t Ab = sb + buf * 24576 + wm * 128;
        const uint32_t Bb = sb + buf * 24576 + 8192 + wn * 128;
        #pragma unroll
        for (int s = 0; s < 4; s++) {
            uint32_t a[2][4], b[8][2];
            #pragma unroll
            for (int i = 0; i < 2; i++)
                ldsm4(a[i][0], a[i][1], a[i][2], a[i][3], Ab + i * 2048 + LK[s]);
            #pragma unroll
            for (int jp = 0; jp < 4; jp++) {
                uint32_t b0, b1, b2, b3;
                ldsm4(b0, b1, b2, b3, Bb + jp * 2048 + LK[s]);
                b[2 * jp][0] = b0; b[2 * jp][1] = b2;
                b[2 * jp + 1][0] = b1; b[2 * jp + 1][1] = b3;
            }
            #pragma unroll
            for (int i = 0; i < 2; i++)
                #pragma unroll
                for (int j = 0; j < 8; j++)
                    mma16h(acc[i][j], a[i], b[j][0], b[j][1]);
        }
    };

    load(0, 0);
    load(1, 1);

    #pragma unroll 1
    for (int kt3 = 0; kt3 < NKT - 1; kt3 += 3) {
        step(kt3 + 0, 0, 2);
        step(kt3 + 1, 1, 0);
        step(kt3 + 2, 2, 1);
    }
    step(NKT - 1, 0, 2);    // tile 15 uses buf 0

    // epilogue
    #pragma unroll
    for (int i = 0; i < 2; i++) {
        #pragma unroll
        for (int j = 0; j < 8; j++) {
            const int row = m0 + wm + i * 16 + (lane >> 2);
            const int col = n0 + wn + j * 8 + (lane & 3) * 2;
            #pragma unroll
            for (int hq = 0; hq < 2; hq++) {
                const int m = row + hq * 8;
                const float v0 = acc[i][j][2 * hq], v1 = acc[i][j][2 * hq + 1];
                if (mode == 3) {
                    *(float2*)&Out[(size_t)m * DMODEL + col] = make_float2(v0, v1);
                } else {
                    const int b_ = m >> 11, s = m & (SEQ - 1);
                    const int h = col >> 6, d = col & (DHEAD - 1);
                    const int bh = b_ * NHEADS + h;
                    if (mode == 0) {
                        *(uint32_t*)&g_q[((size_t)bh * SEQ + s) * DHEAD + d]
                            = h2u(v0 * QSCALE, v1 * QSCALE);
                    } else if (mode == 1) {
                        *(uint32_t*)&g_k[((size_t)bh * SEQ + s) * DHEAD + d] = h2u(v0, v1);
                    } else {
                        g_v[((size_t)(bh * DHEAD + d)) * SEQ + s]     = __float2half_rn(v0);
                        g_v[((size_t)(bh * DHEAD + d + 1)) * SEQ + s] = __float2half_rn(v1);
                    }
                }
            }
        }
    }
}

// ============================================================================
// Flash (exact R12 form, measured 199.3us): 128 thr, 32 q-rows/warp, 64-key
// tiles, P in registers, l via ones-MMA, 4-stage unroll-4, smem 64KB.
// ============================================================================
#define SMEM_FLASH 65536
#define NTILE (SEQ / 64)    // 32

__global__ void __launch_bounds__(128, 3) k_flash()
{
    extern __shared__ char sm[];
    const uint32_t sb = (uint32_t)__cvta_generic_to_shared(sm);

    const int bh = blockIdx.y;
    const int q0 = blockIdx.x * 128;
    const int tid = threadIdx.x, lane = tid & 31, warp = tid >> 5;
    const int u = lane >> 2, t = lane & 3;

    const __half* gK = g_k + (size_t)bh * SEQ * DHEAD;
    const __half* gV = g_v + (size_t)bh * DHEAD * SEQ;
    const __half* gQ = g_q + (size_t)bh * SEQ * DHEAD;

    const int lr = tid >> 1, lh = tid & 1;
    auto loadKV = [&](int kt, int s) {
        if (kt < NTILE) {
            const uint32_t base = sb + s * 16384;
            const __half* sK = gK + (size_t)(kt * 64 + lr) * DHEAD + lh * 32;
            const __half* sV = gV + (size_t)lr * SEQ + kt * 64 + lh * 32;
            #pragma unroll
            for (int i = 0; i < 4; i++) {
                const int c = 4 * lh + i;
                cpa16(base + lr * 128 + ((c ^ (lr & 7)) << 4), sK + 8 * i);
            }
            #pragma unroll
            for (int i = 0; i < 4; i++) {
                const int c = 4 * lh + i;
                cpa16(base + 8192 + lr * 128 + ((c ^ (lr & 7)) << 4), sV + 8 * i);
            }
        }
        asm volatile("cp.async.commit_group;");
    };

    // startup: Q -> stage-3 region (overwritten by tile 3's load later)
    {
        const __half* q = gQ + (size_t)(q0 + tid) * DHEAD;
        #pragma unroll
        for (int c = 0; c < 8; c++)
            cpa16(sb + 49152 + tid * 128 + ((c ^ (tid & 7)) << 4), q + 8 * c);
        asm volatile("cp.async.commit_group;");
    }
    loadKV(0, 0);
    loadKV(1, 1);
    loadKV(2, 2);
    asm volatile("cp.async.wait_group 3;");   // Q done
    __syncthreads();

    const int lrow = ((lane >> 3) & 1) * 8 + (lane & 7);
    const int lch  = lane >> 4;
    uint32_t LK[4];
    #pragma unroll
    for (int s = 0; s < 4; s++)
        LK[s] = lrow * 128 + (((2 * s + lch) ^ (lrow & 7)) << 4);

    // Q a-frags for 32 rows: [m-frag][k16-slice][4]
    uint32_t qa[2][4][4];
    #pragma unroll
    for (int m = 0; m < 2; m++)
        #pragma unroll
        for (int s = 0; s < 4; s++)
            ldsm4(qa[m][s][0], qa[m][s][1], qa[m][s][2], qa[m][s][3],
                  sb + 49152 + warp * 4096 + m * 2048 + LK[s]);

    float o[2][8][4];
    #pragma unroll
    for (int m = 0; m < 2; m++)
        #pragma unroll
        for (int n = 0; n < 8; n++)
            #pragma unroll
            for (int q = 0; q < 4; q++) o[m][n][q] = 0.f;
    float lacc[2][4];
    #pragma unroll
    for (int m = 0; m < 2; m++)
        #pragma unroll
        for (int q = 0; q < 4; q++) lacc[m][q] = 0.f;

    const uint32_t ones2 = 0x3C003C00u;   // half2(1, 1)

    auto fstep = [&](int kt, int buf, int pbuf) {
        asm volatile("cp.async.wait_group 2;");
        __syncthreads();
        loadKV(kt + 3, pbuf);

        const uint32_t Kb = sb + buf * 16384, Vb = Kb + 8192;
        uint32_t kb[4], vb[4];
        #pragma unroll
        for (int s = 0; s < 4; s++) { kb[s] = Kb + LK[s]; vb[s] = Vb + LK[s]; }

        #pragma unroll
        for (int jp = 0; jp < 4; jp++) {
            float sc[2][2][4];
            #pragma unroll
            for (int m = 0; m < 2; m++)
                #pragma unroll
                for (int n = 0; n < 2; n++)
                    #pragma unroll
                    for (int q = 0; q < 4; q++) sc[m][n][q] = 0.f;
            #pragma unroll
            for (int s = 0; s < 4; s++) {
                uint32_t b0, b1, b2, b3;
                ldsm4(b0, b1, b2, b3, kb[s] + jp * 2048);
                #pragma unroll
                for (int m = 0; m < 2; m++) {
                    mma16h(sc[m][0], qa[m][s], b0, b2);
                    mma16h(sc[m][1], qa[m][s], b1, b3);
                }
            }
            // ex2h2 pack: the result IS the PV a-fragment for k-slice jp
            uint32_t ap[2][4];
            #pragma unroll
            for (int m = 0; m < 2; m++) {
                ap[m][0] = ex2h2(cvt_h2(sc[m][0][0], sc[m][0][1]));
                ap[m][1] = ex2h2(cvt_h2(sc[m][0][2], sc[m][0][3]));
                ap[m][2] = ex2h2(cvt_h2(sc[m][1][0], sc[m][1][1]));
                ap[m][3] = ex2h2(cvt_h2(sc[m][1][2], sc[m][1][3]));
                // l row-sums on the tensor pipe (B = ones)
                mma16h(lacc[m], ap[m], ones2, ones2);
            }
            // PV for k-slice jp
            #pragma unroll
            for (int g = 0; g < 4; g++) {
                uint32_t b0, b1, b2, b3;
                ldsm4(b0, b1, b2, b3, vb[jp] + g * 2048);
                #pragma unroll
                for (int m = 0; m < 2; m++) {
                    mma16h(o[m][2 * g],     ap[m], b0, b2);
                    mma16h(o[m][2 * g + 1], ap[m], b1, b3);
                }
            }
        }
    };

    #pragma unroll 1
    for (int it = 0; it < NTILE / 4; ++it) {
        fstep(it * 4 + 0, 0, 3);
        fstep(it * 4 + 1, 1, 0);
        fstep(it * 4 + 2, 2, 1);
        fstep(it * 4 + 3, 3, 2);
    }

    // ---- normalize (lacc holds exact row sums) ----
    const int b_ = bh >> 4, h = bh & 15;
    #pragma unroll
    for (int m = 0; m < 2; m++) {
        const float i0 = 1.0f / lacc[m][0], i1 = 1.0f / lacc[m][2];
        const int row0 = q0 + warp * 32 + m * 16 + u;
        #pragma unroll
        for (int n = 0; n < 8; n++) {
            const int d0 = 8 * n + 2 * t;
            *(uint32_t*)&g_c[(size_t)(b_ * SEQ + row0) * DMODEL + h * DHEAD + d0]
                = h2u(o[m][n][0] * i0, o[m][n][1] * i0);
            *(uint32_t*)&g_c[(size_t)(b_ * SEQ + row0 + 8) * DMODEL + h * DHEAD + d0]
                = h2u(o[m][n][2] * i1, o[m][n][3] * i1);
        }
    }
}

// ============================================================================
extern "C" void kernel_launch(void* const* d_in, const int* in_sizes, int n_in,
                              void* d_out, int out_size)
{
    const float* x  = (const float*)d_in[0];
    const float* Wq = (const float*)d_in[1];
    const float* Wk = (const float*)d_in[2];
    const float* Wv = (const float*)d_in[3];
    const float* Wo = (const float*)d_in[4];
    float* out = (float*)d_out;

    static int attr_set = 0;
    if (!attr_set) {
        cudaFuncSetAttribute(k_flash, cudaFuncAttributeMaxDynamicSharedMemorySize, SMEM_FLASH);
        cudaFuncSetAttribute(k_proj, cudaFuncAttributeMaxDynamicSharedMemorySize, SMEM_PROJ);
        attr_set = 1;
    }

    k_roundx<<<8192, 256>>>((const float4*)x);
    k_trw<<<dim3(32, 32, 4), dim3(32, 8)>>>(Wq, Wk, Wv, Wo);
    k_proj<<<dim3(8, 128, 3), 128, SMEM_PROJ>>>(0, nullptr);
    k_flash<<<dim3(16, 64), 128, SMEM_FLASH>>>();
    k_proj<<<dim3(8, 128, 1), 128, SMEM_PROJ>>>(3, out);
}

// round 16
// speedup vs baseline: 1.3158x; 1.3158x over previous
#include <cuda_runtime.h>
#include <cuda_fp16.h>
#include <cstdint>

#define NHEADS 16
#define DHEAD  64
#define NB     4
#define SEQ    2048
#define DMODEL 1024
#define NBH    (NB * NHEADS)   // 64
#define MTOK   (NB * SEQ)      // 8192

#define QSCALE 0.18033688011112042f   /* 0.125 * log2(e) */

// ---- scratch ----
__device__ __half g_xr[(size_t)MTOK * DMODEL];
__device__ __half g_wt[4][(size_t)DMODEL * DMODEL];
__device__ __half g_q[(size_t)NBH * SEQ * DHEAD];    // [bh][s][d], *QSCALE
__device__ __half g_k[(size_t)NBH * SEQ * DHEAD];    // [bh][s][d]
__device__ __half g_v[(size_t)NBH * DHEAD * SEQ];    // [bh][d][s]
__device__ __half g_c[(size_t)MTOK * DMODEL];        // ctx fp16

// ---- overlap scheduling state (reset in k_roundx each launch) ----
__device__ unsigned g_started;     // flash CTAs entered
__device__ unsigned g_done[64];    // per token-block (b*16+qt): heads completed

__device__ __forceinline__ void mma16h(float c[4], const uint32_t a[4],
                                       uint32_t b0, uint32_t b1) {
    asm volatile(
        "mma.sync.aligned.m16n8k16.row.col.f32.f16.f16.f32 "
        "{%0,%1,%2,%3},{%4,%5,%6,%7},{%8,%9},{%0,%1,%2,%3};"
        : "+f"(c[0]), "+f"(c[1]), "+f"(c[2]), "+f"(c[3])
        : "r"(a[0]), "r"(a[1]), "r"(a[2]), "r"(a[3]), "r"(b0), "r"(b1));
}
__device__ __forceinline__ void ldsm4(uint32_t& r0, uint32_t& r1, uint32_t& r2, uint32_t& r3,
                                      uint32_t addr) {
    asm volatile("ldmatrix.sync.aligned.m8n8.x4.shared.b16 {%0,%1,%2,%3}, [%4];"
                 : "=r"(r0), "=r"(r1), "=r"(r2), "=r"(r3) : "r"(addr));
}
__device__ __forceinline__ void cpa16(uint32_t dst, const void* src) {
    asm volatile("cp.async.cg.shared.global [%0], [%1], 16;" :: "r"(dst), "l"(src));
}
__device__ __forceinline__ uint32_t h2u(float a, float b) {
    __half2 h = __floats2half2_rn(a, b);
    return *(uint32_t*)&h;
}
__device__ __forceinline__ uint32_t cvt_h2(float lo, float hi) {
    uint32_t d;
    asm("cvt.rn.f16x2.f32 %0, %1, %2;" : "=r"(d) : "f"(hi), "f"(lo));
    return d;
}
__device__ __forceinline__ uint32_t ex2h2(uint32_t x) {
    uint32_t d; asm("ex2.approx.f16x2 %0, %1;" : "=r"(d) : "r"(x)); return d;
}

// ============================================================================
// Pre-pass 1: x -> fp16 (+ scheduling-state reset)
// ============================================================================
__global__ void k_roundx(const float4* __restrict__ X)
{
    if (blockIdx.x == 0) {
        if (threadIdx.x < 64) g_done[threadIdx.x] = 0u;
        else if (threadIdx.x == 64) g_started = 0u;
    }
    const size_t i = (size_t)blockIdx.x * blockDim.x + threadIdx.x;
    float4 v = X[i];
    ((uint2*)g_xr)[i] = make_uint2(h2u(v.x, v.y), h2u(v.z, v.w));
}

// ============================================================================
// Pre-pass 2: transpose weights to [n][k] fp16
// ============================================================================
__global__ void k_trw(const float* __restrict__ Wq, const float* __restrict__ Wk,
                      const float* __restrict__ Wv, const float* __restrict__ Wo)
{
    const int p = blockIdx.z;
    const float* W = (p == 0) ? Wq : (p == 1) ? Wk : (p == 2) ? Wv : Wo;
    __shared__ float t[32][33];
    const int n0 = blockIdx.x * 32, k0 = blockIdx.y * 32;
    const int tx = threadIdx.x, ty = threadIdx.y;
    #pragma unroll
    for (int i = 0; i < 4; i++)
        t[ty + 8 * i][tx] = W[(size_t)(k0 + ty + 8 * i) * DMODEL + n0 + tx];
    __syncthreads();
    __half* out = g_wt[p];
    #pragma unroll
    for (int i = 0; i < 4; i++)
        out[(size_t)(n0 + ty + 8 * i) * DMODEL + k0 + tx] = __float2half_rn(t[tx][ty + 8 * i]);
}

// ============================================================================
// QKV projection GEMM (exact R12 shape): 256 thr, 128x128 tile, k-tile 64,
// 3-stage unroll-3, lane-constant LDSM offsets.
// ============================================================================
#define SMEM_PROJ 98304
#define NKT (DMODEL / 64)   // 16

__global__ void __launch_bounds__(256, 2) k_proj(int mode_base, float* __restrict__ Out)
{
    extern __shared__ char sm[];
    const uint32_t sb = (uint32_t)__cvta_generic_to_shared(sm);

    const int mode = mode_base + blockIdx.z;
    const __half* A = (mode < 3) ? g_xr : g_c;
    const __half* Bt = g_wt[mode];

    const int tid = threadIdx.x, lane = tid & 31, warp = tid >> 5;
    const int wm = (warp & 3) * 32, wn = (warp >> 2) * 64;
    const int m0 = blockIdx.y * 128, n0 = blockIdx.x * 128;

    float acc[2][8][4];
    #pragma unroll
    for (int i = 0; i < 2; i++)
        #pragma unroll
        for (int j = 0; j < 8; j++)
            #pragma unroll
            for (int q = 0; q < 4; q++) acc[i][j][q] = 0.f;

    const int lr = tid >> 1, lh = tid & 1;
    const __half* Ap = A  + (size_t)(m0 + lr) * DMODEL + lh * 32;
    const __half* Bp = Bt + (size_t)(n0 + lr) * DMODEL + lh * 32;
    uint32_t offs[4];
    #pragma unroll
    for (int i = 0; i < 4; i++) {
        const int c = 4 * lh + i;
        offs[i] = lr * 128 + ((c ^ (lr & 7)) << 4);
    }
    auto load = [&](int kt, int s) {
        if (kt < NKT) {
            const uint32_t base = sb + s * 32768;
            const __half* a = Ap + kt * 64;
            const __half* b = Bp + kt * 64;
            #pragma unroll
            for (int i = 0; i < 4; i++) cpa16(base + offs[i], a + 8 * i);
            #pragma unroll
            for (int i = 0; i < 4; i++) cpa16(base + 16384 + offs[i], b + 8 * i);
        }
        asm volatile("cp.async.commit_group;");
    };

    const int lrow = ((lane >> 3) & 1) * 8 + (lane & 7);
    const int lch  = lane >> 4;
    uint32_t LK[4];
    #pragma unroll
    for (int s = 0; s < 4; s++)
        LK[s] = lrow * 128 + (((2 * s + lch) ^ (lrow & 7)) << 4);

    auto step = [&](int kt, int buf, int pbuf) {
        asm volatile("cp.async.wait_group 1;");
        __syncthreads();
        load(kt + 2, pbuf);

        const uint32_t Ab = sb + buf * 32768, Bb = Ab + 16384;
        uint32_t aB[4], bB[4];
        #pragma unroll
        for (int s = 0; s < 4; s++) {
            aB[s] = Ab + wm * 128 + LK[s];
            bB[s] = Bb + wn * 128 + LK[s];
        }
        #pragma unroll
        for (int s = 0; s < 4; s++) {
            uint32_t a[2][4], b[8][2];
            #pragma unroll
            for (int i = 0; i < 2; i++)
                ldsm4(a[i][0], a[i][1], a[i][2], a[i][3], aB[s] + i * 2048);
            #pragma unroll
            for (int jp = 0; jp < 4; jp++) {
                uint32_t b0, b1, b2, b3;
                ldsm4(b0, b1, b2, b3, bB[s] + jp * 2048);
                b[2 * jp][0] = b0; b[2 * jp][1] = b2;
                b[2 * jp + 1][0] = b1; b[2 * jp + 1][1] = b3;
            }
            #pragma unroll
            for (int i = 0; i < 2; i++)
                #pragma unroll
                for (int j = 0; j < 8; j++)
                    mma16h(acc[i][j], a[i], b[j][0], b[j][1]);
        }
    };

    load(0, 0);
    load(1, 1);

    #pragma unroll 1
    for (int kt3 = 0; kt3 < NKT - 1; kt3 += 3) {
        step(kt3 + 0, 0, 2);
        step(kt3 + 1, 1, 0);
        step(kt3 + 2, 2, 1);
    }
    step(NKT - 1, 0, 2);

    #pragma unroll
    for (int i = 0; i < 2; i++) {
        #pragma unroll
        for (int j = 0; j < 8; j++) {
            const int row = m0 + wm + i * 16 + (lane >> 2);
            const int col = n0 + wn + j * 8 + (lane & 3) * 2;
            #pragma unroll
            for (int hq = 0; hq < 2; hq++) {
                const int m = row + hq * 8;
                const float v0 = acc[i][j][2 * hq], v1 = acc[i][j][2 * hq + 1];
                if (mode == 3) {
                    *(float2*)&Out[(size_t)m * DMODEL + col] = make_float2(v0, v1);
                } else {
                    const int b_ = m >> 11, s = m & (SEQ - 1);
                    const int h = col >> 6, d = col & (DHEAD - 1);
                    const int bh = b_ * NHEADS + h;
                    if (mode == 0) {
                        *(uint32_t*)&g_q[((size_t)bh * SEQ + s) * DHEAD + d]
                            = h2u(v0 * QSCALE, v1 * QSCALE);
                    } else if (mode == 1) {
                        *(uint32_t*)&g_k[((size_t)bh * SEQ + s) * DHEAD + d] = h2u(v0, v1);
                    } else {
                        g_v[((size_t)(bh * DHEAD + d)) * SEQ + s]     = __float2half_rn(v0);
                        g_v[((size_t)(bh * DHEAD + d + 1)) * SEQ + s] = __float2half_rn(v1);
                    }
                }
            }
        }
    }
}

// ============================================================================
// Output projection (R12 proj body, mode 3 only) with dependency spin:
// waits for all 16 heads of its token block, then runs identically.
// Launched on a low-priority stream to fill the flash tail.
// ============================================================================
__global__ void __launch_bounds__(256, 2) k_oproj(float* __restrict__ Out)
{
    extern __shared__ char sm[];
    const uint32_t sb = (uint32_t)__cvta_generic_to_shared(sm);

    // dependency: all heads of this 128-token block must be in g_c
    if (threadIdx.x == 0) {
        while (atomicAdd(&g_done[blockIdx.y], 0u) < 16u) __nanosleep(256);
        __threadfence();
    }
    __syncthreads();

    const __half* A = g_c;
    const __half* Bt = g_wt[3];

    const int tid = threadIdx.x, lane = tid & 31, warp = tid >> 5;
    const int wm = (warp & 3) * 32, wn = (warp >> 2) * 64;
    const int m0 = blockIdx.y * 128, n0 = blockIdx.x * 128;

    float acc[2][8][4];
    #pragma unroll
    for (int i = 0; i < 2; i++)
        #pragma unroll
        for (int j = 0; j < 8; j++)
            #pragma unroll
            for (int q = 0; q < 4; q++) acc[i][j][q] = 0.f;

    const int lr = tid >> 1, lh = tid & 1;
    const __half* Ap = A  + (size_t)(m0 + lr) * DMODEL + lh * 32;
    const __half* Bp = Bt + (size_t)(n0 + lr) * DMODEL + lh * 32;
    uint32_t offs[4];
    #pragma unroll
    for (int i = 0; i < 4; i++) {
        const int c = 4 * lh + i;
        offs[i] = lr * 128 + ((c ^ (lr & 7)) << 4);
    }
    auto load = [&](int kt, int s) {
        if (kt < NKT) {
            const uint32_t base = sb + s * 32768;
            const __half* a = Ap + kt * 64;
            const __half* b = Bp + kt * 64;
            #pragma unroll
            for (int i = 0; i < 4; i++) cpa16(base + offs[i], a + 8 * i);
            #pragma unroll
            for (int i = 0; i < 4; i++) cpa16(base + 16384 + offs[i], b + 8 * i);
        }
        asm volatile("cp.async.commit_group;");
    };

    const int lrow = ((lane >> 3) & 1) * 8 + (lane & 7);
    const int lch  = lane >> 4;
    uint32_t LK[4];
    #pragma unroll
    for (int s = 0; s < 4; s++)
        LK[s] = lrow * 128 + (((2 * s + lch) ^ (lrow & 7)) << 4);

    auto step = [&](int kt, int buf, int pbuf) {
        asm volatile("cp.async.wait_group 1;");
        __syncthreads();
        load(kt + 2, pbuf);

        const uint32_t Ab = sb + buf * 32768, Bb = Ab + 16384;
        uint32_t aB[4], bB[4];
        #pragma unroll
        for (int s = 0; s < 4; s++) {
            aB[s] = Ab + wm * 128 + LK[s];
            bB[s] = Bb + wn * 128 + LK[s];
        }
        #pragma unroll
        for (int s = 0; s < 4; s++) {
            uint32_t a[2][4], b[8][2];
            #pragma unroll
            for (int i = 0; i < 2; i++)
                ldsm4(a[i][0], a[i][1], a[i][2], a[i][3], aB[s] + i * 2048);
            #pragma unroll
            for (int jp = 0; jp < 4; jp++) {
                uint32_t b0, b1, b2, b3;
                ldsm4(b0, b1, b2, b3, bB[s] + jp * 2048);
                b[2 * jp][0] = b0; b[2 * jp][1] = b2;
                b[2 * jp + 1][0] = b1; b[2 * jp + 1][1] = b3;
            }
            #pragma unroll
            for (int i = 0; i < 2; i++)
                #pragma unroll
                for (int j = 0; j < 8; j++)
                    mma16h(acc[i][j], a[i], b[j][0], b[j][1]);
        }
    };

    load(0, 0);
    load(1, 1);

    #pragma unroll 1
    for (int kt3 = 0; kt3 < NKT - 1; kt3 += 3) {
        step(kt3 + 0, 0, 2);
        step(kt3 + 1, 1, 0);
        step(kt3 + 2, 2, 1);
    }
    step(NKT - 1, 0, 2);

    #pragma unroll
    for (int i = 0; i < 2; i++) {
        #pragma unroll
        for (int j = 0; j < 8; j++) {
            const int row = m0 + wm + i * 16 + (lane >> 2);
            const int col = n0 + wn + j * 8 + (lane & 3) * 2;
            #pragma unroll
            for (int hq = 0; hq < 2; hq++) {
                const int m = row + hq * 8;
                *(float2*)&Out[(size_t)m * DMODEL + col]
                    = make_float2(acc[i][j][2 * hq], acc[i][j][2 * hq + 1]);
            }
        }
    }
}

// ============================================================================
// Gate: holds the low-priority stream until flash has filled the machine
// (>=440 of 444 resident slots claimed). Guarantees oproj cannot starve flash.
// ============================================================================
__global__ void k_gate()
{
    unsigned it = 0;
    while (atomicAdd(&g_started, 0u) < 440u && it < 50000000u) {
        it++;
        __nanosleep(200);
    }
}

// ============================================================================
// Flash (exact R12 form): 128 thr, 32 q-rows/warp, 64-key tiles, P in regs,
// l via ones-MMA, 4-stage unroll-4, smem 64KB. + g_started/g_done signalling.
// ============================================================================
#define SMEM_FLASH 65536
#define NTILE (SEQ / 64)    // 32

__global__ void __launch_bounds__(128, 3) k_flash()
{
    extern __shared__ char sm[];
    const uint32_t sb = (uint32_t)__cvta_generic_to_shared(sm);

    const int bh = blockIdx.y;
    const int q0 = blockIdx.x * 128;
    const int tid = threadIdx.x, lane = tid & 31, warp = tid >> 5;
    const int u = lane >> 2, t = lane & 3;

    if (tid == 0) atomicAdd(&g_started, 1u);

    const __half* gK = g_k + (size_t)bh * SEQ * DHEAD;
    const __half* gV = g_v + (size_t)bh * DHEAD * SEQ;
    const __half* gQ = g_q + (size_t)bh * SEQ * DHEAD;

    const int lr = tid >> 1, lh = tid & 1;
    auto loadKV = [&](int kt, int s) {
        if (kt < NTILE) {
            const uint32_t base = sb + s * 16384;
            const __half* sK = gK + (size_t)(kt * 64 + lr) * DHEAD + lh * 32;
            const __half* sV = gV + (size_t)lr * SEQ + kt * 64 + lh * 32;
            #pragma unroll
            for (int i = 0; i < 4; i++) {
                const int c = 4 * lh + i;
                cpa16(base + lr * 128 + ((c ^ (lr & 7)) << 4), sK + 8 * i);
            }
            #pragma unroll
            for (int i = 0; i < 4; i++) {
                const int c = 4 * lh + i;
                cpa16(base + 8192 + lr * 128 + ((c ^ (lr & 7)) << 4), sV + 8 * i);
            }
        }
        asm volatile("cp.async.commit_group;");
    };

    // startup: Q -> stage-3 region (overwritten by tile 3's load later)
    {
        const __half* q = gQ + (size_t)(q0 + tid) * DHEAD;
        #pragma unroll
        for (int c = 0; c < 8; c++)
            cpa16(sb + 49152 + tid * 128 + ((c ^ (tid & 7)) << 4), q + 8 * c);
        asm volatile("cp.async.commit_group;");
    }
    loadKV(0, 0);
    loadKV(1, 1);
    loadKV(2, 2);
    asm volatile("cp.async.wait_group 3;");   // Q done
    __syncthreads();

    const int lrow = ((lane >> 3) & 1) * 8 + (lane & 7);
    const int lch  = lane >> 4;
    uint32_t LK[4];
    #pragma unroll
    for (int s = 0; s < 4; s++)
        LK[s] = lrow * 128 + (((2 * s + lch) ^ (lrow & 7)) << 4);

    uint32_t qa[2][4][4];
    #pragma unroll
    for (int m = 0; m < 2; m++)
        #pragma unroll
        for (int s = 0; s < 4; s++)
            ldsm4(qa[m][s][0], qa[m][s][1], qa[m][s][2], qa[m][s][3],
                  sb + 49152 + warp * 4096 + m * 2048 + LK[s]);

    float o[2][8][4];
    #pragma unroll
    for (int m = 0; m < 2; m++)
        #pragma unroll
        for (int n = 0; n < 8; n++)
            #pragma unroll
            for (int q = 0; q < 4; q++) o[m][n][q] = 0.f;
    float lacc[2][4];
    #pragma unroll
    for (int m = 0; m < 2; m++)
        #pragma unroll
        for (int q = 0; q < 4; q++) lacc[m][q] = 0.f;

    const uint32_t ones2 = 0x3C003C00u;   // half2(1, 1)

    auto fstep = [&](int kt, int buf, int pbuf) {
        asm volatile("cp.async.wait_group 2;");
        __syncthreads();
        loadKV(kt + 3, pbuf);

        const uint32_t Kb = sb + buf * 16384, Vb = Kb + 8192;
        uint32_t kb[4], vb[4];
        #pragma unroll
        for (int s = 0; s < 4; s++) { kb[s] = Kb + LK[s]; vb[s] = Vb + LK[s]; }

        #pragma unroll
        for (int jp = 0; jp < 4; jp++) {
            float sc[2][2][4];
            #pragma unroll
            for (int m = 0; m < 2; m++)
                #pragma unroll
                for (int n = 0; n < 2; n++)
                    #pragma unroll
                    for (int q = 0; q < 4; q++) sc[m][n][q] = 0.f;
            #pragma unroll
            for (int s = 0; s < 4; s++) {
                uint32_t b0, b1, b2, b3;
                ldsm4(b0, b1, b2, b3, kb[s] + jp * 2048);
                #pragma unroll
                for (int m = 0; m < 2; m++) {
                    mma16h(sc[m][0], qa[m][s], b0, b2);
                    mma16h(sc[m][1], qa[m][s], b1, b3);
                }
            }
            uint32_t ap[2][4];
            #pragma unroll
            for (int m = 0; m < 2; m++) {
                ap[m][0] = ex2h2(cvt_h2(sc[m][0][0], sc[m][0][1]));
                ap[m][1] = ex2h2(cvt_h2(sc[m][0][2], sc[m][0][3]));
                ap[m][2] = ex2h2(cvt_h2(sc[m][1][0], sc[m][1][1]));
                ap[m][3] = ex2h2(cvt_h2(sc[m][1][2], sc[m][1][3]));
                mma16h(lacc[m], ap[m], ones2, ones2);
            }
            #pragma unroll
            for (int g = 0; g < 4; g++) {
                uint32_t b0, b1, b2, b3;
                ldsm4(b0, b1, b2, b3, vb[jp] + g * 2048);
                #pragma unroll
                for (int m = 0; m < 2; m++) {
                    mma16h(o[m][2 * g],     ap[m], b0, b2);
                    mma16h(o[m][2 * g + 1], ap[m], b1, b3);
                }
            }
        }
    };

    #pragma unroll 1
    for (int it = 0; it < NTILE / 4; ++it) {
        fstep(it * 4 + 0, 0, 3);
        fstep(it * 4 + 1, 1, 0);
        fstep(it * 4 + 2, 2, 1);
        fstep(it * 4 + 3, 3, 2);
    }

    const int b_ = bh >> 4, h = bh & 15;
    #pragma unroll
    for (int m = 0; m < 2; m++) {
        const float i0 = 1.0f / lacc[m][0], i1 = 1.0f / lacc[m][2];
        const int row0 = q0 + warp * 32 + m * 16 + u;
        #pragma unroll
        for (int n = 0; n < 8; n++) {
            const int d0 = 8 * n + 2 * t;
            *(uint32_t*)&g_c[(size_t)(b_ * SEQ + row0) * DMODEL + h * DHEAD + d0]
                = h2u(o[m][n][0] * i0, o[m][n][1] * i0);
            *(uint32_t*)&g_c[(size_t)(b_ * SEQ + row0 + 8) * DMODEL + h * DHEAD + d0]
                = h2u(o[m][n][2] * i1, o[m][n][3] * i1);
        }
    }

    // signal: this (b, qtile) head slice of ctx is complete
    __syncthreads();
    if (tid == 0) {
        __threadfence();
        atomicAdd(&g_done[b_ * 16 + blockIdx.x], 1u);
    }
}

// ============================================================================
extern "C" void kernel_launch(void* const* d_in, const int* in_sizes, int n_in,
                              void* d_out, int out_size)
{
    const float* x  = (const float*)d_in[0];
    const float* Wq = (const float*)d_in[1];
    const float* Wk = (const float*)d_in[2];
    const float* Wv = (const float*)d_in[3];
    const float* Wo = (const float*)d_in[4];
    float* out = (float*)d_out;

    static int attr_set = 0;
    static cudaStream_t s_lo;
    static cudaEvent_t e_fork, e_join;
    if (!attr_set) {
        cudaFuncSetAttribute(k_flash, cudaFuncAttributeMaxDynamicSharedMemorySize, SMEM_FLASH);
        cudaFuncSetAttribute(k_proj,  cudaFuncAttributeMaxDynamicSharedMemorySize, SMEM_PROJ);
        cudaFuncSetAttribute(k_oproj, cudaFuncAttributeMaxDynamicSharedMemorySize, SMEM_PROJ);
        int prio_lo, prio_hi;
        cudaDeviceGetStreamPriorityRange(&prio_lo, &prio_hi);
        cudaStreamCreateWithPriority(&s_lo, cudaStreamNonBlocking, prio_lo);
        cudaEventCreateWithFlags(&e_fork, cudaEventDisableTiming);
        cudaEventCreateWithFlags(&e_join, cudaEventDisableTiming);
        attr_set = 1;
    }

    k_roundx<<<8192, 256>>>((const float4*)x);
    k_trw<<<dim3(32, 32, 4), dim3(32, 8)>>>(Wq, Wk, Wv, Wo);
    k_proj<<<dim3(8, 64, 3), 256, SMEM_PROJ>>>(0, nullptr);

    cudaEventRecord(e_fork, 0);
    k_flash<<<dim3(16, 64), 128, SMEM_FLASH>>>();

    cudaStreamWaitEvent(s_lo, e_fork, 0);
    k_gate<<<1, 1, 0, s_lo>>>();
    k_oproj<<<dim3(8, 64), 256, SMEM_PROJ, s_lo>>>(out);
    cudaEventRecord(e_join, s_lo);
    cudaStreamWaitEvent(0, e_join, 0);
}

// round 17
// speedup vs baseline: 1.3599x; 1.0335x over previous
#include <cuda_runtime.h>
#include <cuda_fp16.h>
#include <cstdint>

#define NHEADS 16
#define DHEAD  64
#define NB     4
#define SEQ    2048
#define DMODEL 1024
#define NBH    (NB * NHEADS)   // 64
#define MTOK   (NB * SEQ)      // 8192

#define QSCALE 0.18033688011112042f   /* 0.125 * log2(e) */

// ---- scratch ----
__device__ __half g_xr[(size_t)MTOK * DMODEL];
__device__ __half g_wt[4][(size_t)DMODEL * DMODEL];
__device__ __half g_q[(size_t)NBH * SEQ * DHEAD];    // [bh][s][d], *QSCALE
__device__ __half g_k[(size_t)NBH * SEQ * DHEAD];    // [bh][s][d]
__device__ __half g_v[(size_t)NBH * DHEAD * SEQ];    // [bh][d][s]
__device__ __half g_c[(size_t)MTOK * DMODEL];        // ctx fp16

// ---- overlap scheduling state (reset in k_roundx each launch) ----
__device__ unsigned g_started;       // flash CTAs entered
__device__ unsigned g_qkv_started;   // qkv-proj CTAs entered
__device__ unsigned g_done[64];      // per token-block (b*16+qt): heads completed
__device__ unsigned g_qd[512];       // Q proj tile flags  [y=0..63][n=0..7]
__device__ unsigned g_kv[32];        // K+V proj counters  [b=0..3][n=0..7] -> 32

__device__ __forceinline__ void mma16h(float c[4], const uint32_t a[4],
                                       uint32_t b0, uint32_t b1) {
    asm volatile(
        "mma.sync.aligned.m16n8k16.row.col.f32.f16.f16.f32 "
        "{%0,%1,%2,%3},{%4,%5,%6,%7},{%8,%9},{%0,%1,%2,%3};"
        : "+f"(c[0]), "+f"(c[1]), "+f"(c[2]), "+f"(c[3])
        : "r"(a[0]), "r"(a[1]), "r"(a[2]), "r"(a[3]), "r"(b0), "r"(b1));
}
__device__ __forceinline__ void ldsm4(uint32_t& r0, uint32_t& r1, uint32_t& r2, uint32_t& r3,
                                      uint32_t addr) {
    asm volatile("ldmatrix.sync.aligned.m8n8.x4.shared.b16 {%0,%1,%2,%3}, [%4];"
                 : "=r"(r0), "=r"(r1), "=r"(r2), "=r"(r3) : "r"(addr));
}
__device__ __forceinline__ void cpa16(uint32_t dst, const void* src) {
    asm volatile("cp.async.cg.shared.global [%0], [%1], 16;" :: "r"(dst), "l"(src));
}
__device__ __forceinline__ uint32_t h2u(float a, float b) {
    __half2 h = __floats2half2_rn(a, b);
    return *(uint32_t*)&h;
}
__device__ __forceinline__ uint32_t cvt_h2(float lo, float hi) {
    uint32_t d;
    asm("cvt.rn.f16x2.f32 %0, %1, %2;" : "=r"(d) : "f"(hi), "f"(lo));
    return d;
}
__device__ __forceinline__ uint32_t ex2h2(uint32_t x) {
    uint32_t d; asm("ex2.approx.f16x2 %0, %1;" : "=r"(d) : "r"(x)); return d;
}

// ============================================================================
// Pre-pass 1: x -> fp16 (+ scheduling-state reset)
// ============================================================================
__global__ void k_roundx(const float4* __restrict__ X)
{
    if (blockIdx.x == 0) {
        for (int i = threadIdx.x; i < 512; i += 256) g_qd[i] = 0u;
        if (threadIdx.x < 32) g_kv[threadIdx.x] = 0u;
        if (threadIdx.x >= 64 && threadIdx.x < 128) g_done[threadIdx.x - 64] = 0u;
        if (threadIdx.x == 128) g_started = 0u;
        if (threadIdx.x == 129) g_qkv_started = 0u;
    }
    const size_t i = (size_t)blockIdx.x * blockDim.x + threadIdx.x;
    float4 v = X[i];
    ((uint2*)g_xr)[i] = make_uint2(h2u(v.x, v.y), h2u(v.z, v.w));
}

// ============================================================================
// Pre-pass 2: transpose weights to [n][k] fp16
// ============================================================================
__global__ void k_trw(const float* __restrict__ Wq, const float* __restrict__ Wk,
                      const float* __restrict__ Wv, const float* __restrict__ Wo)
{
    const int p = blockIdx.z;
    const float* W = (p == 0) ? Wq : (p == 1) ? Wk : (p == 2) ? Wv : Wo;
    __shared__ float t[32][33];
    const int n0 = blockIdx.x * 32, k0 = blockIdx.y * 32;
    const int tx = threadIdx.x, ty = threadIdx.y;
    #pragma unroll
    for (int i = 0; i < 4; i++)
        t[ty + 8 * i][tx] = W[(size_t)(k0 + ty + 8 * i) * DMODEL + n0 + tx];
    __syncthreads();
    __half* out = g_wt[p];
    #pragma unroll
    for (int i = 0; i < 4; i++)
        out[(size_t)(n0 + ty + 8 * i) * DMODEL + k0 + tx] = __float2half_rn(t[tx][ty + 8 * i]);
}

// ============================================================================
// QKV projection GEMM (R12 shape): 256 thr, 128x128 tile, k-tile 64,
// 3-stage unroll-3. Epilogue signals per-tile completion flags/counters.
// ============================================================================
#define SMEM_PROJ 98304
#define NKT (DMODEL / 64)   // 16

__global__ void __launch_bounds__(256, 2) k_proj(int mode_base, float* __restrict__ Out)
{
    extern __shared__ char sm[];
    const uint32_t sb = (uint32_t)__cvta_generic_to_shared(sm);

    if (threadIdx.x == 0) atomicAdd(&g_qkv_started, 1u);

    const int mode = mode_base + blockIdx.z;
    const __half* A = (mode < 3) ? g_xr : g_c;
    const __half* Bt = g_wt[mode];

    const int tid = threadIdx.x, lane = tid & 31, warp = tid >> 5;
    const int wm = (warp & 3) * 32, wn = (warp >> 2) * 64;
    const int m0 = blockIdx.y * 128, n0 = blockIdx.x * 128;

    float acc[2][8][4];
    #pragma unroll
    for (int i = 0; i < 2; i++)
        #pragma unroll
        for (int j = 0; j < 8; j++)
            #pragma unroll
            for (int q = 0; q < 4; q++) acc[i][j][q] = 0.f;

    const int lr = tid >> 1, lh = tid & 1;
    const __half* Ap = A  + (size_t)(m0 + lr) * DMODEL + lh * 32;
    const __half* Bp = Bt + (size_t)(n0 + lr) * DMODEL + lh * 32;
    uint32_t offs[4];
    #pragma unroll
    for (int i = 0; i < 4; i++) {
        const int c = 4 * lh + i;
        offs[i] = lr * 128 + ((c ^ (lr & 7)) << 4);
    }
    auto load = [&](int kt, int s) {
        if (kt < NKT) {
            const uint32_t base = sb + s * 32768;
            const __half* a = Ap + kt * 64;
            const __half* b = Bp + kt * 64;
            #pragma unroll
            for (int i = 0; i < 4; i++) cpa16(base + offs[i], a + 8 * i);
            #pragma unroll
            for (int i = 0; i < 4; i++) cpa16(base + 16384 + offs[i], b + 8 * i);
        }
        asm volatile("cp.async.commit_group;");
    };

    const int lrow = ((lane >> 3) & 1) * 8 + (lane & 7);
    const int lch  = lane >> 4;
    uint32_t LK[4];
    #pragma unroll
    for (int s = 0; s < 4; s++)
        LK[s] = lrow * 128 + (((2 * s + lch) ^ (lrow & 7)) << 4);

    auto step = [&](int kt, int buf, int pbuf) {
        asm volatile("cp.async.wait_group 1;");
        __syncthreads();
        load(kt + 2, pbuf);

        const uint32_t Ab = sb + buf * 32768, Bb = Ab + 16384;
        uint32_t aB[4], bB[4];
        #pragma unroll
        for (int s = 0; s < 4; s++) {
            aB[s] = Ab + wm * 128 + LK[s];
            bB[s] = Bb + wn * 128 + LK[s];
        }
        #pragma unroll
        for (int s = 0; s < 4; s++) {
            uint32_t a[2][4], b[8][2];
            #pragma unroll
            for (int i = 0; i < 2; i++)
                ldsm4(a[i][0], a[i][1], a[i][2], a[i][3], aB[s] + i * 2048);
            #pragma unroll
            for (int jp = 0; jp < 4; jp++) {
                uint32_t b0, b1, b2, b3;
                ldsm4(b0, b1, b2, b3, bB[s] + jp * 2048);
                b[2 * jp][0] = b0; b[2 * jp][1] = b2;
                b[2 * jp + 1][0] = b1; b[2 * jp + 1][1] = b3;
            }
            #pragma unroll
            for (int i = 0; i < 2; i++)
                #pragma unroll
                for (int j = 0; j < 8; j++)
                    mma16h(acc[i][j], a[i], b[j][0], b[j][1]);
        }
    };

    load(0, 0);
    load(1, 1);

    #pragma unroll 1
    for (int kt3 = 0; kt3 < NKT - 1; kt3 += 3) {
        step(kt3 + 0, 0, 2);
        step(kt3 + 1, 1, 0);
        step(kt3 + 2, 2, 1);
    }
    step(NKT - 1, 0, 2);

    #pragma unroll
    for (int i = 0; i < 2; i++) {
        #pragma unroll
        for (int j = 0; j < 8; j++) {
            const int row = m0 + wm + i * 16 + (lane >> 2);
            const int col = n0 + wn + j * 8 + (lane & 3) * 2;
            #pragma unroll
            for (int hq = 0; hq < 2; hq++) {
                const int m = row + hq * 8;
                const float v0 = acc[i][j][2 * hq], v1 = acc[i][j][2 * hq + 1];
                if (mode == 3) {
                    *(float2*)&Out[(size_t)m * DMODEL + col] = make_float2(v0, v1);
                } else {
                    const int b_ = m >> 11, s = m & (SEQ - 1);
                    const int h = col >> 6, d = col & (DHEAD - 1);
                    const int bh = b_ * NHEADS + h;
                    if (mode == 0) {
                        *(uint32_t*)&g_q[((size_t)bh * SEQ + s) * DHEAD + d]
                            = h2u(v0 * QSCALE, v1 * QSCALE);
                    } else if (mode == 1) {
                        *(uint32_t*)&g_k[((size_t)bh * SEQ + s) * DHEAD + d] = h2u(v0, v1);
                    } else {
                        g_v[((size_t)(bh * DHEAD + d)) * SEQ + s]     = __float2half_rn(v0);
                        g_v[((size_t)(bh * DHEAD + d + 1)) * SEQ + s] = __float2half_rn(v1);
                    }
                }
            }
        }
    }

    // signal tile completion (flash dependency tracking)
    __syncthreads();
    if (tid == 0 && mode < 3) {
        __threadfence();
        if (mode == 0) atomicExch(&g_qd[blockIdx.y * 8 + blockIdx.x], 1u);
        else           atomicAdd(&g_kv[(blockIdx.y >> 4) * 8 + blockIdx.x], 1u);
    }
}

// ============================================================================
// Output projection (R12 proj body) with dependency spin on g_done.
// ============================================================================
__global__ void __launch_bounds__(256, 2) k_oproj(float* __restrict__ Out)
{
    extern __shared__ char sm[];
    const uint32_t sb = (uint32_t)__cvta_generic_to_shared(sm);

    if (threadIdx.x == 0) {
        while (atomicAdd(&g_done[blockIdx.y], 0u) < 16u) __nanosleep(256);
        __threadfence();
    }
    __syncthreads();

    const __half* A = g_c;
    const __half* Bt = g_wt[3];

    const int tid = threadIdx.x, lane = tid & 31, warp = tid >> 5;
    const int wm = (warp & 3) * 32, wn = (warp >> 2) * 64;
    const int m0 = blockIdx.y * 128, n0 = blockIdx.x * 128;

    float acc[2][8][4];
    #pragma unroll
    for (int i = 0; i < 2; i++)
        #pragma unroll
        for (int j = 0; j < 8; j++)
            #pragma unroll
            for (int q = 0; q < 4; q++) acc[i][j][q] = 0.f;

    const int lr = tid >> 1, lh = tid & 1;
    const __half* Ap = A  + (size_t)(m0 + lr) * DMODEL + lh * 32;
    const __half* Bp = Bt + (size_t)(n0 + lr) * DMODEL + lh * 32;
    uint32_t offs[4];
    #pragma unroll
    for (int i = 0; i < 4; i++) {
        const int c = 4 * lh + i;
        offs[i] = lr * 128 + ((c ^ (lr & 7)) << 4);
    }
    auto load = [&](int kt, int s) {
        if (kt < NKT) {
            const uint32_t base = sb + s * 32768;
            const __half* a = Ap + kt * 64;
            const __half* b = Bp + kt * 64;
            #pragma unroll
            for (int i = 0; i < 4; i++) cpa16(base + offs[i], a + 8 * i);
            #pragma unroll
            for (int i = 0; i < 4; i++) cpa16(base + 16384 + offs[i], b + 8 * i);
        }
        asm volatile("cp.async.commit_group;");
    };

    const int lrow = ((lane >> 3) & 1) * 8 + (lane & 7);
    const int lch  = lane >> 4;
    uint32_t LK[4];
    #pragma unroll
    for (int s = 0; s < 4; s++)
        LK[s] = lrow * 128 + (((2 * s + lch) ^ (lrow & 7)) << 4);

    auto step = [&](int kt, int buf, int pbuf) {
        asm volatile("cp.async.wait_group 1;");
        __syncthreads();
        load(kt + 2, pbuf);

        const uint32_t Ab = sb + buf * 32768, Bb = Ab + 16384;
        uint32_t aB[4], bB[4];
        #pragma unroll
        for (int s = 0; s < 4; s++) {
            aB[s] = Ab + wm * 128 + LK[s];
            bB[s] = Bb + wn * 128 + LK[s];
        }
        #pragma unroll
        for (int s = 0; s < 4; s++) {
            uint32_t a[2][4], b[8][2];
            #pragma unroll
            for (int i = 0; i < 2; i++)
                ldsm4(a[i][0], a[i][1], a[i][2], a[i][3], aB[s] + i * 2048);
            #pragma unroll
            for (int jp = 0; jp < 4; jp++) {
                uint32_t b0, b1, b2, b3;
                ldsm4(b0, b1, b2, b3, bB[s] + jp * 2048);
                b[2 * jp][0] = b0; b[2 * jp][1] = b2;
                b[2 * jp + 1][0] = b1; b[2 * jp + 1][1] = b3;
            }
            #pragma unroll
            for (int i = 0; i < 2; i++)
                #pragma unroll
                for (int j = 0; j < 8; j++)
                    mma16h(acc[i][j], a[i], b[j][0], b[j][1]);
        }
    };

    load(0, 0);
    load(1, 1);

    #pragma unroll 1
    for (int kt3 = 0; kt3 < NKT - 1; kt3 += 3) {
        step(kt3 + 0, 0, 2);
        step(kt3 + 1, 1, 0);
        step(kt3 + 2, 2, 1);
    }
    step(NKT - 1, 0, 2);

    #pragma unroll
    for (int i = 0; i < 2; i++) {
        #pragma unroll
        for (int j = 0; j < 8; j++) {
            const int row = m0 + wm + i * 16 + (lane >> 2);
            const int col = n0 + wn + j * 8 + (lane & 3) * 2;
            #pragma unroll
            for (int hq = 0; hq < 2; hq++) {
                const int m = row + hq * 8;
                *(float2*)&Out[(size_t)m * DMODEL + col]
                    = make_float2(acc[i][j][2 * hq], acc[i][j][2 * hq + 1]);
            }
        }
    }
}

// ============================================================================
// Gates
// ============================================================================
__global__ void k_gate_qkv()    // release flash when qkv almost fully dispatched
{
    unsigned it = 0;
    while (atomicAdd(&g_qkv_started, 0u) < 1241u && it < 50000000u) {
        it++;
        __nanosleep(200);
    }
}
__global__ void k_gate_flash()  // release oproj when ALL flash CTAs dispatched
{
    unsigned it = 0;
    while (atomicAdd(&g_started, 0u) < 1024u && it < 50000000u) {
        it++;
        __nanosleep(200);
    }
}

// ============================================================================
// Flash (R12 body) + per-CTA dependency spin on its Q tile / K,V columns.
// ============================================================================
#define SMEM_FLASH 65536
#define NTILE (SEQ / 64)    // 32

__global__ void __launch_bounds__(128, 3) k_flash()
{
    extern __shared__ char sm[];
    const uint32_t sb = (uint32_t)__cvta_generic_to_shared(sm);

    const int bh = blockIdx.y;
    const int q0 = blockIdx.x * 128;
    const int tid = threadIdx.x, lane = tid & 31, warp = tid >> 5;
    const int u = lane >> 2, t = lane & 3;

    if (tid == 0) {
        atomicAdd(&g_started, 1u);
        const int b0_ = bh >> 4, h0_ = bh & 15, np = h0_ >> 1;
        while (atomicAdd(&g_qd[(b0_ * 16 + blockIdx.x) * 8 + np], 0u) == 0u) __nanosleep(128);
        while (atomicAdd(&g_kv[b0_ * 8 + np], 0u) < 32u) __nanosleep(128);
        __threadfence();
    }
    __syncthreads();

    const __half* gK = g_k + (size_t)bh * SEQ * DHEAD;
    const __half* gV = g_v + (size_t)bh * DHEAD * SEQ;
    const __half* gQ = g_q + (size_t)bh * SEQ * DHEAD;

    const int lr = tid >> 1, lh = tid & 1;
    auto loadKV = [&](int kt, int s) {
        if (kt < NTILE) {
            const uint32_t base = sb + s * 16384;
            const __half* sK = gK + (size_t)(kt * 64 + lr) * DHEAD + lh * 32;
            const __half* sV = gV + (size_t)lr * SEQ + kt * 64 + lh * 32;
            #pragma unroll
            for (int i = 0; i < 4; i++) {
                const int c = 4 * lh + i;
                cpa16(base + lr * 128 + ((c ^ (lr & 7)) << 4), sK + 8 * i);
            }
            #pragma unroll
            for (int i = 0; i < 4; i++) {
                const int c = 4 * lh + i;
                cpa16(base + 8192 + lr * 128 + ((c ^ (lr & 7)) << 4), sV + 8 * i);
            }
        }
        asm volatile("cp.async.commit_group;");
    };

    // startup: Q -> stage-3 region (overwritten by tile 3's load later)
    {
        const __half* q = gQ + (size_t)(q0 + tid) * DHEAD;
        #pragma unroll
        for (int c = 0; c < 8; c++)
            cpa16(sb + 49152 + tid * 128 + ((c ^ (tid & 7)) << 4), q + 8 * c);
        asm volatile("cp.async.commit_group;");
    }
    loadKV(0, 0);
    loadKV(1, 1);
    loadKV(2, 2);
    asm volatile("cp.async.wait_group 3;");   // Q done
    __syncthreads();

    const int lrow = ((lane >> 3) & 1) * 8 + (lane & 7);
    const int lch  = lane >> 4;
    uint32_t LK[4];
    #pragma unroll
    for (int s = 0; s < 4; s++)
        LK[s] = lrow * 128 + (((2 * s + lch) ^ (lrow & 7)) << 4);

    uint32_t qa[2][4][4];
    #pragma unroll
    for (int m = 0; m < 2; m++)
        #pragma unroll
        for (int s = 0; s < 4; s++)
            ldsm4(qa[m][s][0], qa[m][s][1], qa[m][s][2], qa[m][s][3],
                  sb + 49152 + warp * 4096 + m * 2048 + LK[s]);

    float o[2][8][4];
    #pragma unroll
    for (int m = 0; m < 2; m++)
        #pragma unroll
        for (int n = 0; n < 8; n++)
            #pragma unroll
            for (int q = 0; q < 4; q++) o[m][n][q] = 0.f;
    float lacc[2][4];
    #pragma unroll
    for (int m = 0; m < 2; m++)
        #pragma unroll
        for (int q = 0; q < 4; q++) lacc[m][q] = 0.f;

    const uint32_t ones2 = 0x3C003C00u;   // half2(1, 1)

    auto fstep = [&](int kt, int buf, int pbuf) {
        asm volatile("cp.async.wait_group 2;");
        __syncthreads();
        loadKV(kt + 3, pbuf);

        const uint32_t Kb = sb + buf * 16384, Vb = Kb + 8192;
        uint32_t kb[4], vb[4];
        #pragma unroll
        for (int s = 0; s < 4; s++) { kb[s] = Kb + LK[s]; vb[s] = Vb + LK[s]; }

        #pragma unroll
        for (int jp = 0; jp < 4; jp++) {
            float sc[2][2][4];
            #pragma unroll
            for (int m = 0; m < 2; m++)
                #pragma unroll
                for (int n = 0; n < 2; n++)
                    #pragma unroll
                    for (int q = 0; q < 4; q++) sc[m][n][q] = 0.f;
            #pragma unroll
            for (int s = 0; s < 4; s++) {
                uint32_t b0, b1, b2, b3;
                ldsm4(b0, b1, b2, b3, kb[s] + jp * 2048);
                #pragma unroll
                for (int m = 0; m < 2; m++) {
                    mma16h(sc[m][0], qa[m][s], b0, b2);
                    mma16h(sc[m][1], qa[m][s], b1, b3);
                }
            }
            uint32_t ap[2][4];
            #pragma unroll
            for (int m = 0; m < 2; m++) {
                ap[m][0] = ex2h2(cvt_h2(sc[m][0][0], sc[m][0][1]));
                ap[m][1] = ex2h2(cvt_h2(sc[m][0][2], sc[m][0][3]));
                ap[m][2] = ex2h2(cvt_h2(sc[m][1][0], sc[m][1][1]));
                ap[m][3] = ex2h2(cvt_h2(sc[m][1][2], sc[m][1][3]));
                mma16h(lacc[m], ap[m], ones2, ones2);
            }
            #pragma unroll
            for (int g = 0; g < 4; g++) {
                uint32_t b0, b1, b2, b3;
                ldsm4(b0, b1, b2, b3, vb[jp] + g * 2048);
                #pragma unroll
                for (int m = 0; m < 2; m++) {
                    mma16h(o[m][2 * g],     ap[m], b0, b2);
                    mma16h(o[m][2 * g + 1], ap[m], b1, b3);
                }
            }
        }
    };

    #pragma unroll 1
    for (int it = 0; it < NTILE / 4; ++it) {
        fstep(it * 4 + 0, 0, 3);
        fstep(it * 4 + 1, 1, 0);
        fstep(it * 4 + 2, 2, 1);
        fstep(it * 4 + 3, 3, 2);
    }

    const int b_ = bh >> 4, h = bh & 15;
    #pragma unroll
    for (int m = 0; m < 2; m++) {
        const float i0 = 1.0f / lacc[m][0], i1 = 1.0f / lacc[m][2];
        const int row0 = q0 + warp * 32 + m * 16 + u;
        #pragma unroll
        for (int n = 0; n < 8; n++) {
            const int d0 = 8 * n + 2 * t;
            *(uint32_t*)&g_c[(size_t)(b_ * SEQ + row0) * DMODEL + h * DHEAD + d0]
                = h2u(o[m][n][0] * i0, o[m][n][1] * i0);
            *(uint32_t*)&g_c[(size_t)(b_ * SEQ + row0 + 8) * DMODEL + h * DHEAD + d0]
                = h2u(o[m][n][2] * i1, o[m][n][3] * i1);
        }
    }

    __syncthreads();
    if (tid == 0) {
        __threadfence();
        atomicAdd(&g_done[b_ * 16 + blockIdx.x], 1u);
    }
}

// ============================================================================
extern "C" void kernel_launch(void* const* d_in, const int* in_sizes, int n_in,
                              void* d_out, int out_size)
{
    const float* x  = (const float*)d_in[0];
    const float* Wq = (const float*)d_in[1];
    const float* Wk = (const float*)d_in[2];
    const float* Wv = (const float*)d_in[3];
    const float* Wo = (const float*)d_in[4];
    float* out = (float*)d_out;

    static int attr_set = 0;
    static cudaStream_t s_hi, s_fl, s_lo;
    static cudaEvent_t e0, e_qkv, e_flash, e_oproj;
    if (!attr_set) {
        cudaFuncSetAttribute(k_flash, cudaFuncAttributeMaxDynamicSharedMemorySize, SMEM_FLASH);
        cudaFuncSetAttribute(k_proj,  cudaFuncAttributeMaxDynamicSharedMemorySize, SMEM_PROJ);
        cudaFuncSetAttribute(k_oproj, cudaFuncAttributeMaxDynamicSharedMemorySize, SMEM_PROJ);
        int prio_lo, prio_hi;
        cudaDeviceGetStreamPriorityRange(&prio_lo, &prio_hi);
        cudaStreamCreateWithPriority(&s_hi, cudaStreamNonBlocking, prio_hi);  // qkv
        cudaStreamCreateWithPriority(&s_fl, cudaStreamNonBlocking, 0);        // flash
        cudaStreamCreateWithPriority(&s_lo, cudaStreamNonBlocking, prio_lo);  // oproj
        cudaEventCreateWithFlags(&e0,      cudaEventDisableTiming);
        cudaEventCreateWithFlags(&e_qkv,   cudaEventDisableTiming);
        cudaEventCreateWithFlags(&e_flash, cudaEventDisableTiming);
        cudaEventCreateWithFlags(&e_oproj, cudaEventDisableTiming);
        attr_set = 1;
    }

    // stream 0: prep (also resets counters)
    k_roundx<<<8192, 256>>>((const float4*)x);
    k_trw<<<dim3(32, 32, 4), dim3(32, 8)>>>(Wq, Wk, Wv, Wo);
    cudaEventRecord(e0, 0);

    // high-priority: QKV projections
    cudaStreamWaitEvent(s_hi, e0, 0);
    k_proj<<<dim3(8, 64, 3), 256, SMEM_PROJ, s_hi>>>(0, nullptr);
    cudaEventRecord(e_qkv, s_hi);

    // default-priority: flash, gated until qkv almost fully dispatched
    cudaStreamWaitEvent(s_fl, e0, 0);
    k_gate_qkv<<<1, 1, 0, s_fl>>>();
    k_flash<<<dim3(16, 64), 128, SMEM_FLASH, s_fl>>>();
    cudaEventRecord(e_flash, s_fl);

    // low-priority: oproj, gated until flash fully dispatched
    cudaStreamWaitEvent(s_lo, e0, 0);
    k_gate_flash<<<1, 1, 0, s_lo>>>();
    k_oproj<<<dim3(8, 64), 256, SMEM_PROJ, s_lo>>>(out);
    cudaEventRecord(e_oproj, s_lo);

    // join everything back to stream 0
    cudaStreamWaitEvent(0, e_qkv, 0);
    cudaStreamWaitEvent(0, e_flash, 0);
    cudaStreamWaitEvent(0, e_oproj, 0);
}